// round 9
// baseline (speedup 1.0000x reference)
#include <cuda_runtime.h>
#include <cuda_bf16.h>
#include <cstdint>

// Problem constants (fixed by the dataset)
#define B 64
#define S 8192
#define C 48
#define L 42
#define LP1 (L + 1)          // 43
#define IGNORE_LBL (-100)

#define ROW_THREADS 1024
#define ROW_WARPS   (ROW_THREADS / 32)   // 32
#define NCH   4                          // chunks per row
#define CHUNK (S / NCH)                  // 2048
#define SUBS  (CHUNK / ROW_THREADS)      // 2 positions per thread
#define NSEG  (SUBS * ROW_WARPS)         // 64 warp-segments per chunk
#define NCHT  (B * NCH)                  // 256 total chunks

// ---------------------------------------------------------------------------
// Device-global scratch
// ---------------------------------------------------------------------------
__device__ float  g_partial[NCHT];   // per-chunk normalized partial (float)
__device__ int    g_pcount[NCHT];    // per-chunk valid-token count
__device__ int    g_first[NCHT];     // per-chunk first valid label (-1 if none)
__device__ int    g_last[NCHT];      // per-chunk last valid label
__device__ unsigned g_ticket;        // finish counter (reset by last block)

// Gather load with 64B L2 fetch-size hint (halves DRAM fill vs 128B line).
__device__ __forceinline__ float ld_gather_64B(const float* p) {
    float v;
    asm volatile("ld.global.L2::64B.f32 %0, [%1];" : "=f"(v) : "l"(p));
    return v;
}

// ---------------------------------------------------------------------------
// One block per (row, chunk). 256 blocks = 1 wave at 2 blocks/SM.
// Transitions are normalized on the fly: A_raw - lse[src]; no trans table.
// ---------------------------------------------------------------------------
__global__ __launch_bounds__(ROW_THREADS)
void crf_fused_kernel(const float* log_probs,
                      const float* __restrict__ A_scores,
                      const int*   __restrict__ labels,
                      float*       __restrict__ out) {
    const int cid  = blockIdx.x;        // chunk id
    const int b    = cid / NCH;         // batch row
    const int ch   = cid % NCH;         // chunk within row
    const int tid  = threadIdx.x;
    const int lane = tid & 31;
    const int wid  = tid >> 5;

    __shared__ float    A_sh[L + L * LP1];   // 1848 raw scores
    __shared__ float    lse_sh[LP1];         // [0..41]=trans rows, [42]=start
    __shared__ int      seg_first[NSEG];
    __shared__ int      seg_last[NSEG];
    __shared__ unsigned seg_mask[2];
    __shared__ float    red[ROW_WARPS];
    __shared__ int      redc[ROW_WARPS];
    __shared__ int      is_last;
    __shared__ double   row_sum[B];
    __shared__ int      row_cnt[B];

    // ---- 1. stage A_scores; issue label loads (in flight) ----
    #pragma unroll
    for (int i = tid; i < L + L * LP1; i += ROW_THREADS) A_sh[i] = A_scores[i];

    const int* lab = labels + (size_t)b * S + (size_t)ch * CHUNK;
    int ys[SUBS];
    #pragma unroll
    for (int i = 0; i < SUBS; i++) ys[i] = __ldg(lab + i * ROW_THREADS + tid);

    __syncthreads();   // A_sh ready (label LDGs still in flight)

    // ---- 2. 43 log-sum-exps (warp w: rows w and w+32), overlaps label flight ----
    #pragma unroll
    for (int rr = 0; rr < 2; rr++) {
        int r = wid + rr * ROW_WARPS;
        if (r <= L) {
            int n = (r == L) ? L : LP1;
            const float* row = (r == L) ? A_sh : (A_sh + L + r * LP1);
            float v0 = (lane < n)      ? row[lane]      : -1e30f;
            float v1 = (lane + 32 < n) ? row[lane + 32] : -1e30f;
            float m = fmaxf(v0, v1);
            #pragma unroll
            for (int o = 16; o > 0; o >>= 1)
                m = fmaxf(m, __shfl_xor_sync(0xffffffffu, m, o));
            float s = ((lane < n) ? __expf(v0 - m) : 0.f)
                    + ((lane + 32 < n) ? __expf(v1 - m) : 0.f);
            #pragma unroll
            for (int o = 16; o > 0; o >>= 1)
                s += __shfl_xor_sync(0xffffffffu, s, o);
            if (lane == 0) lse_sh[r] = m + __logf(s);
        }
    }
    __syncthreads();   // lse_sh ready

    // ---- 3. issue emission gathers (labels landed), 64B hint ----
    const float* lpb = log_probs + (size_t)b * S * C + (size_t)ch * CHUNK * C;
    float emis[SUBS];
    #pragma unroll
    for (int i = 0; i < SUBS; i++) {
        int p = i * ROW_THREADS + tid;
        emis[i] = (ys[i] != IGNORE_LBL)
                ? ld_gather_64B(lpb + (size_t)p * C + ys[i]) : 0.0f;
    }

    // ---- 4. transitions (normalized on the fly) + segment endpoints ----
    float local = 0.0f;
    int   cnt   = 0;
    #pragma unroll
    for (int i = 0; i < SUBS; i++) {
        int y = ys[i];
        bool valid = (y != IGNORE_LBL);
        cnt += valid ? 1 : 0;

        unsigned m = __ballot_sync(0xffffffffu, valid);
        unsigned rest = m & (0xFFFFFFFEu << lane);   // valid lanes strictly after me
        int partner = rest ? (__ffs(rest) - 1) : -1;
        int ynext = __shfl_sync(0xffffffffu, y, partner & 31);
        if (valid && partner >= 0)
            local += A_sh[L + (y - 1) * LP1 + (ynext - 1)] - lse_sh[y - 1];

        int firstlane = __ffs(m) - 1;
        int lastlane  = 31 - __clz(m | 1u);
        int yf = __shfl_sync(0xffffffffu, y, firstlane & 31);
        int yl = __shfl_sync(0xffffffffu, y, lastlane & 31);
        if (lane == 0) {
            int seg = i * ROW_WARPS + wid;           // position order
            seg_first[seg] = m ? yf : -1;
            seg_last[seg]  = m ? yl : -1;
        }
    }
    __syncthreads();   // seg arrays ready

    // ---- 5. parallel warp-boundary stitching (threads 0..63) ----
    if (tid < 64) {
        bool ne = (seg_first[tid] >= 0);
        unsigned m = __ballot_sync(0xffffffffu, ne);
        if ((tid & 31) == 0) seg_mask[tid >> 5] = m;
    }
    __syncthreads();
    if (tid < NSEG) {
        int s = tid;
        if (seg_first[s] >= 0) {
            unsigned low = (s & 31) ? (seg_mask[s >> 5] & ((1u << (s & 31)) - 1u)) : 0u;
            int pred = -1;
            if (low)                         pred = (s & ~31) + (31 - __clz(low));
            else if (s >= 32 && seg_mask[0]) pred = 31 - __clz(seg_mask[0]);
            if (pred >= 0) {
                int y1 = seg_last[pred], y2 = seg_first[s];
                local += A_sh[L + (y1 - 1) * LP1 + (y2 - 1)] - lse_sh[y1 - 1];
            }
        }
    }
    if (tid == 0) {
        unsigned m0 = seg_mask[0], m1 = seg_mask[1];
        int bf = -1, bl = -1;
        if (m0)      bf = seg_first[__ffs(m0) - 1];
        else if (m1) bf = seg_first[32 + __ffs(m1) - 1];
        if (m1)      bl = seg_last[32 + 31 - __clz(m1)];
        else if (m0) bl = seg_last[31 - __clz(m0)];
        g_first[cid] = bf;
        g_last[cid]  = bl;
    }

    // ---- 6. fold emissions, block reduce (float) ----
    #pragma unroll
    for (int i = 0; i < SUBS; i++) local += emis[i];
    #pragma unroll
    for (int o = 16; o > 0; o >>= 1) {
        local += __shfl_down_sync(0xffffffffu, local, o);
        cnt   += __shfl_down_sync(0xffffffffu, cnt, o);
    }
    if (lane == 0) { red[wid] = local; redc[wid] = cnt; }
    __syncthreads();
    if (wid == 0) {
        float v = red[lane];
        int   c = redc[lane];
        #pragma unroll
        for (int o = 16; o > 0; o >>= 1) {
            v += __shfl_down_sync(0xffffffffu, v, o);
            c += __shfl_down_sync(0xffffffffu, c, o);
        }
        if (lane == 0) {
            g_partial[cid] = v;
            g_pcount[cid]  = c;
            __threadfence();
            unsigned t = atomicAdd(&g_ticket, 1u);
            is_last = (t == NCHT - 1) ? 1 : 0;
        }
    }
    __syncthreads();

    // ---- 7. last block: stitch chunk boundaries + start/final, finalize ----
    if (is_last) {
        __threadfence();
        if (tid < B) {
            double s = 0.0; int c = 0, prev = -1, f0 = -1;
            #pragma unroll
            for (int k = 0; k < NCH; k++) {
                int idx = tid * NCH + k;
                s += (double)g_partial[idx];
                c += g_pcount[idx];
                int f = g_first[idx];
                if (f >= 0) {
                    if (prev >= 0)
                        s += (double)(A_sh[L + (prev - 1) * LP1 + (f - 1)] - lse_sh[prev - 1]);
                    else f0 = f;
                    prev = g_last[idx];
                }
            }
            if (f0 >= 0) {
                s += (double)(A_sh[f0 - 1] - lse_sh[L]);                          // start
                s += (double)(A_sh[L + (prev - 1) * LP1 + L] - lse_sh[prev - 1]); // final
            }
            row_sum[tid] = s;
            row_cnt[tid] = c;
        }
        __syncthreads();
        if (wid == 0) {
            double s = row_sum[lane] + row_sum[lane + 32];
            int    c = row_cnt[lane] + row_cnt[lane + 32];
            #pragma unroll
            for (int o = 16; o > 0; o >>= 1) {
                s += __shfl_down_sync(0xffffffffu, s, o);
                c += __shfl_down_sync(0xffffffffu, c, o);
            }
            if (lane == 0) {
                out[0] = (float)(s / (double)c);
                g_ticket = 0;    // reset for graph replay
            }
        }
    }
}

// ---------------------------------------------------------------------------
// Launch
// ---------------------------------------------------------------------------
extern "C" void kernel_launch(void* const* d_in, const int* in_sizes, int n_in,
                              void* d_out, int out_size) {
    const float* log_probs = (const float*)d_in[0];   // (B, S, C) f32
    const float* A_scores  = (const float*)d_in[1];   // (N_ARCS,) f32
    const int*   labels    = (const int*)d_in[2];     // (B, S) i32
    float* out = (float*)d_out;

    crf_fused_kernel<<<NCHT, ROW_THREADS>>>(log_probs, A_scores, labels, out);
}

// round 11
// speedup vs baseline: 1.0185x; 1.0185x over previous
#include <cuda_runtime.h>
#include <cuda_bf16.h>
#include <cstdint>

// Problem constants (fixed by the dataset)
#define B 64
#define S 8192
#define C 48
#define L 42
#define LP1 (L + 1)          // 43
#define IGNORE_LBL (-100)

#define ROW_THREADS 1024
#define ROW_WARPS   (ROW_THREADS / 32)   // 32
#define NCH   4                          // chunks per row
#define CHUNK (S / NCH)                  // 2048 positions; 2 consecutive per thread
#define NSEG  ROW_WARPS                  // 32 warp-segments per chunk
#define NCHT  (B * NCH)                  // 256 blocks

// ---------------------------------------------------------------------------
// Device-global scratch
// ---------------------------------------------------------------------------
__device__ float  g_partial[NCHT];   // per-chunk normalized partial
__device__ int    g_pcount[NCHT];    // per-chunk valid-token count
__device__ int    g_first[NCHT];     // per-chunk first valid label (-1 if none)
__device__ int    g_last[NCHT];      // per-chunk last valid label
__device__ unsigned g_ticket;        // finish counter (reset by last block)

// Gather load with 64B L2 fetch-size hint (halves DRAM fill vs 128B line).
__device__ __forceinline__ float ld_gather_64B(const float* p) {
    float v;
    asm volatile("ld.global.L2::64B.f32 %0, [%1];" : "=f"(v) : "l"(p));
    return v;
}

// ---------------------------------------------------------------------------
// One block per (row, chunk). Thread t owns consecutive positions {2t, 2t+1}
// of its chunk: int2 label load, local intra-pair transition, single
// cross-thread ballot chain, one segment per warp.
// ---------------------------------------------------------------------------
__global__ __launch_bounds__(ROW_THREADS)
void crf_fused_kernel(const float* log_probs,
                      const float* __restrict__ A_scores,
                      const int*   __restrict__ labels,
                      float*       __restrict__ out) {
    const int cid  = blockIdx.x;        // chunk id
    const int b    = cid / NCH;         // batch row
    const int ch   = cid % NCH;         // chunk within row
    const int tid  = threadIdx.x;
    const int lane = tid & 31;
    const int wid  = tid >> 5;

    __shared__ float  A_sh[L + L * LP1];   // 1848 raw scores
    __shared__ float  lse_sh[LP1];         // [0..41]=trans rows, [42]=start
    __shared__ int    seg_first[NSEG];
    __shared__ int    seg_last[NSEG];
    __shared__ float  red[ROW_WARPS];
    __shared__ int    redc[ROW_WARPS];
    __shared__ int    is_last;
    __shared__ double row_sum[B];
    __shared__ int    row_cnt[B];

    // ---- 1. stage A_scores; issue label loads (int2, in flight) ----
    #pragma unroll
    for (int i = tid; i < L + L * LP1; i += ROW_THREADS) A_sh[i] = A_scores[i];

    const int2* lab = (const int2*)(labels + (size_t)b * S + (size_t)ch * CHUNK);
    int2 yy = __ldg(lab + tid);            // positions 2*tid, 2*tid+1

    __syncthreads();   // A_sh ready (label LDG still in flight)

    // ---- 2. 43 log-sum-exps (warp w: rows w and w+32), overlaps label flight ----
    #pragma unroll
    for (int rr = 0; rr < 2; rr++) {
        int r = wid + rr * ROW_WARPS;
        if (r <= L) {
            int n = (r == L) ? L : LP1;
            const float* row = (r == L) ? A_sh : (A_sh + L + r * LP1);
            float v0 = (lane < n)      ? row[lane]      : -1e30f;
            float v1 = (lane + 32 < n) ? row[lane + 32] : -1e30f;
            float m = fmaxf(v0, v1);
            #pragma unroll
            for (int o = 16; o > 0; o >>= 1)
                m = fmaxf(m, __shfl_xor_sync(0xffffffffu, m, o));
            float s = ((lane < n) ? __expf(v0 - m) : 0.f)
                    + ((lane + 32 < n) ? __expf(v1 - m) : 0.f);
            #pragma unroll
            for (int o = 16; o > 0; o >>= 1)
                s += __shfl_xor_sync(0xffffffffu, s, o);
            if (lane == 0) lse_sh[r] = m + __logf(s);
        }
    }
    __syncthreads();   // lse_sh ready

    // ---- 3. issue emission gathers (labels landed), 64B hint ----
    const float* lpb = log_probs + (size_t)b * S * C + (size_t)ch * CHUNK * C;
    const int y0 = yy.x, y1 = yy.y;
    const bool v0 = (y0 != IGNORE_LBL), v1 = (y1 != IGNORE_LBL);
    float e0 = 0.0f, e1 = 0.0f;
    if (v0) e0 = ld_gather_64B(lpb + (size_t)(2 * tid)     * C + y0);
    if (v1) e1 = ld_gather_64B(lpb + (size_t)(2 * tid + 1) * C + y1);

    // ---- 4. transitions ----
    float local = 0.0f;
    int   cnt   = (v0 ? 1 : 0) + (v1 ? 1 : 0);

    // intra-pair (positions 2t -> 2t+1)
    if (v0 && v1)
        local += A_sh[L + (y0 - 1) * LP1 + (y1 - 1)] - lse_sh[y0 - 1];

    // cross-thread chain: (my last valid) -> (next nonempty thread's first valid)
    int firstv = v0 ? y0 : (v1 ? y1 : -1);
    int lastv  = v1 ? y1 : (v0 ? y0 : -1);
    bool ne = (firstv >= 0);
    unsigned m = __ballot_sync(0xffffffffu, ne);
    unsigned rest = m & (0xFFFFFFFEu << lane);       // nonempty lanes strictly after me
    int partner = rest ? (__ffs(rest) - 1) : -1;
    int pfirst  = __shfl_sync(0xffffffffu, firstv, partner & 31);
    if (ne && partner >= 0)
        local += A_sh[L + (lastv - 1) * LP1 + (pfirst - 1)] - lse_sh[lastv - 1];

    // warp-segment endpoints (one per warp)
    int flane = __ffs(m) - 1;
    int llane = 31 - __clz(m | 1u);
    int yf = __shfl_sync(0xffffffffu, firstv, flane & 31);
    int yl = __shfl_sync(0xffffffffu, lastv,  llane & 31);
    if (lane == 0) {
        seg_first[wid] = m ? yf : -1;
        seg_last[wid]  = m ? yl : -1;
    }
    __syncthreads();   // seg arrays ready

    // ---- 5. warp-boundary stitching (warp 0, 32 segments, one ballot) ----
    if (wid == 0) {
        bool sne = (seg_first[lane] >= 0);
        unsigned sm = __ballot_sync(0xffffffffu, sne);
        if (sne) {
            unsigned low = sm & ((1u << lane) - 1u);
            if (low) {
                int pred = 31 - __clz(low);
                int a = seg_last[pred], c2 = seg_first[lane];
                local += A_sh[L + (a - 1) * LP1 + (c2 - 1)] - lse_sh[a - 1];
            }
        }
        if (lane == 0) {
            g_first[cid] = sm ? seg_first[__ffs(sm) - 1] : -1;
            g_last[cid]  = sm ? seg_last[31 - __clz(sm)] : -1;
        }
    }

    // ---- 6. fold emissions, block reduce (float) ----
    local += e0 + e1;
    #pragma unroll
    for (int o = 16; o > 0; o >>= 1) {
        local += __shfl_down_sync(0xffffffffu, local, o);
        cnt   += __shfl_down_sync(0xffffffffu, cnt, o);
    }
    if (lane == 0) { red[wid] = local; redc[wid] = cnt; }
    __syncthreads();
    if (wid == 0) {
        float v = red[lane];
        int   c = redc[lane];
        #pragma unroll
        for (int o = 16; o > 0; o >>= 1) {
            v += __shfl_down_sync(0xffffffffu, v, o);
            c += __shfl_down_sync(0xffffffffu, c, o);
        }
        if (lane == 0) {
            g_partial[cid] = v;
            g_pcount[cid]  = c;
            __threadfence();
            unsigned t = atomicAdd(&g_ticket, 1u);
            is_last = (t == NCHT - 1) ? 1 : 0;
        }
    }
    __syncthreads();

    // ---- 7. last block: stitch chunk boundaries + start/final, finalize ----
    if (is_last) {
        __threadfence();
        if (tid < B) {
            double s = 0.0; int c = 0, prev = -1, f0 = -1;
            #pragma unroll
            for (int k = 0; k < NCH; k++) {
                int idx = tid * NCH + k;
                s += (double)g_partial[idx];
                c += g_pcount[idx];
                int f = g_first[idx];
                if (f >= 0) {
                    if (prev >= 0)
                        s += (double)(A_sh[L + (prev - 1) * LP1 + (f - 1)] - lse_sh[prev - 1]);
                    else f0 = f;
                    prev = g_last[idx];
                }
            }
            if (f0 >= 0) {
                s += (double)(A_sh[f0 - 1] - lse_sh[L]);                          // start
                s += (double)(A_sh[L + (prev - 1) * LP1 + L] - lse_sh[prev - 1]); // final
            }
            row_sum[tid] = s;
            row_cnt[tid] = c;
        }
        __syncthreads();
        if (wid == 0) {
            double s = row_sum[lane] + row_sum[lane + 32];
            int    c = row_cnt[lane] + row_cnt[lane + 32];
            #pragma unroll
            for (int o = 16; o > 0; o >>= 1) {
                s += __shfl_down_sync(0xffffffffu, s, o);
                c += __shfl_down_sync(0xffffffffu, c, o);
            }
            if (lane == 0) {
                out[0] = (float)(s / (double)c);
                g_ticket = 0;    // reset for graph replay
            }
        }
    }
}

// ---------------------------------------------------------------------------
// Launch
// ---------------------------------------------------------------------------
extern "C" void kernel_launch(void* const* d_in, const int* in_sizes, int n_in,
                              void* d_out, int out_size) {
    const float* log_probs = (const float*)d_in[0];   // (B, S, C) f32
    const float* A_scores  = (const float*)d_in[1];   // (N_ARCS,) f32
    const int*   labels    = (const int*)d_in[2];     // (B, S) i32
    float* out = (float*)d_out;

    crf_fused_kernel<<<NCHT, ROW_THREADS>>>(log_probs, A_scores, labels, out);
}

// round 12
// speedup vs baseline: 1.1159x; 1.0957x over previous
#include <cuda_runtime.h>
#include <cuda_bf16.h>
#include <cstdint>

// Problem constants (fixed by the dataset)
#define B 64
#define S 8192
#define C 48
#define L 42
#define LP1 (L + 1)          // 43
#define IGNORE_LBL (-100)

#define THREADS 512
#define WARPS   (THREADS / 32)   // 16
#define NCH     4                // chunks per row
#define CHUNK   (S / NCH)        // 2048 positions; 4 consecutive per thread
#define NSEG    WARPS            // 16 warp-segments per chunk
#define NCHT    (B * NCH)        // 256 blocks

// ---------------------------------------------------------------------------
// Device-global scratch
// ---------------------------------------------------------------------------
__device__ float  g_partial[NCHT];   // per-chunk normalized partial
__device__ int    g_pcount[NCHT];    // per-chunk valid-token count
__device__ int    g_first[NCHT];     // per-chunk first valid label (-1 if none)
__device__ int    g_last[NCHT];      // per-chunk last valid label
__device__ unsigned g_ticket;        // finish counter (reset by last block)

// Gather load with 64B L2 fetch-size hint (halves DRAM fill vs 128B line).
__device__ __forceinline__ float ld_gather_64B(const float* p) {
    float v;
    asm volatile("ld.global.L2::64B.f32 %0, [%1];" : "=f"(v) : "l"(p));
    return v;
}

// ---------------------------------------------------------------------------
// One block per (row, chunk). Thread t owns consecutive positions
// {4t..4t+3} of its chunk: one int4 label load, thread-local transition
// chain (skips invalids), single cross-thread ballot chain, one segment
// per warp. 4 gathers in flight per thread.
// ---------------------------------------------------------------------------
__global__ __launch_bounds__(THREADS)
void crf_fused_kernel(const float* log_probs,
                      const float* __restrict__ A_scores,
                      const int*   __restrict__ labels,
                      float*       __restrict__ out) {
    const int cid  = blockIdx.x;        // chunk id
    const int b    = cid / NCH;         // batch row
    const int ch   = cid % NCH;         // chunk within row
    const int tid  = threadIdx.x;
    const int lane = tid & 31;
    const int wid  = tid >> 5;

    __shared__ float  A_sh[L + L * LP1];   // 1848 raw scores
    __shared__ float  lse_sh[LP1];         // [0..41]=trans rows, [42]=start
    __shared__ int    seg_first[NSEG];
    __shared__ int    seg_last[NSEG];
    __shared__ float  red[WARPS];
    __shared__ int    redc[WARPS];
    __shared__ int    is_last;
    __shared__ double row_sum[B];
    __shared__ int    row_cnt[B];

    // ---- 1. issue label load (int4) first, then stage A_scores ----
    const int4* lab = (const int4*)(labels + (size_t)b * S + (size_t)ch * CHUNK);
    int4 yy = __ldg(lab + tid);            // positions 4t .. 4t+3

    #pragma unroll
    for (int i = tid; i < L + L * LP1; i += THREADS) A_sh[i] = A_scores[i];
    __syncthreads();   // A_sh ready (label LDG still in flight)

    // ---- 2. 43 log-sum-exps (warp w: rows w, w+16, w+32), overlaps labels ----
    #pragma unroll
    for (int rr = 0; rr < 3; rr++) {
        int r = wid + rr * WARPS;
        if (r <= L) {
            int n = (r == L) ? L : LP1;
            const float* row = (r == L) ? A_sh : (A_sh + L + r * LP1);
            float v0 = (lane < n)      ? row[lane]      : -1e30f;
            float v1 = (lane + 32 < n) ? row[lane + 32] : -1e30f;
            float m = fmaxf(v0, v1);
            #pragma unroll
            for (int o = 16; o > 0; o >>= 1)
                m = fmaxf(m, __shfl_xor_sync(0xffffffffu, m, o));
            float s = ((lane < n) ? __expf(v0 - m) : 0.f)
                    + ((lane + 32 < n) ? __expf(v1 - m) : 0.f);
            #pragma unroll
            for (int o = 16; o > 0; o >>= 1)
                s += __shfl_xor_sync(0xffffffffu, s, o);
            if (lane == 0) lse_sh[r] = m + __logf(s);
        }
    }
    __syncthreads();   // lse_sh ready

    // ---- 3. issue all 4 emission gathers (labels landed), 64B hint ----
    const float* lpb = log_probs + (size_t)b * S * C + (size_t)ch * CHUNK * C
                     + (size_t)(4 * tid) * C;
    int  y[4]  = {yy.x, yy.y, yy.z, yy.w};
    bool v[4];
    float e[4];
    #pragma unroll
    for (int i = 0; i < 4; i++) {
        v[i] = (y[i] != IGNORE_LBL);
        e[i] = v[i] ? ld_gather_64B(lpb + i * C + y[i]) : 0.0f;
    }

    // ---- 4. thread-local transition chain (skips invalids) ----
    float local = 0.0f;
    int   cnt   = 0;
    int   prev = -1, firstv = -1;
    #pragma unroll
    for (int i = 0; i < 4; i++) {
        if (v[i]) {
            cnt++;
            if (prev >= 0) local += A_sh[L + (prev - 1) * LP1 + (y[i] - 1)] - lse_sh[prev - 1];
            else           firstv = y[i];
            prev = y[i];
        }
    }
    const int lastv = prev;

    // ---- 5. cross-thread chain + warp-segment endpoints (one ballot) ----
    bool ne = (firstv >= 0);
    unsigned m = __ballot_sync(0xffffffffu, ne);
    unsigned rest = m & (0xFFFFFFFEu << lane);       // nonempty lanes strictly after me
    int partner = rest ? (__ffs(rest) - 1) : -1;
    int pfirst  = __shfl_sync(0xffffffffu, firstv, partner & 31);
    if (ne && partner >= 0)
        local += A_sh[L + (lastv - 1) * LP1 + (pfirst - 1)] - lse_sh[lastv - 1];

    int flane = __ffs(m) - 1;
    int llane = 31 - __clz(m | 1u);
    int yf = __shfl_sync(0xffffffffu, firstv, flane & 31);
    int yl = __shfl_sync(0xffffffffu, lastv,  llane & 31);
    if (lane == 0) {
        seg_first[wid] = m ? yf : -1;
        seg_last[wid]  = m ? yl : -1;
    }
    __syncthreads();   // seg arrays ready

    // ---- 6. warp-boundary stitching (warp 0, 16 segments, one ballot) ----
    if (wid == 0) {
        bool sne = (lane < NSEG) && (seg_first[lane] >= 0);
        unsigned sm = __ballot_sync(0xffffffffu, sne);
        if (sne) {
            unsigned low = sm & ((1u << lane) - 1u);
            if (low) {
                int pred = 31 - __clz(low);
                int a = seg_last[pred], c2 = seg_first[lane];
                local += A_sh[L + (a - 1) * LP1 + (c2 - 1)] - lse_sh[a - 1];
            }
        }
        if (lane == 0) {
            g_first[cid] = sm ? seg_first[__ffs(sm) - 1] : -1;
            g_last[cid]  = sm ? seg_last[31 - __clz(sm)] : -1;
        }
    }

    // ---- 7. fold emissions, block reduce (float) ----
    local += (e[0] + e[1]) + (e[2] + e[3]);
    #pragma unroll
    for (int o = 16; o > 0; o >>= 1) {
        local += __shfl_down_sync(0xffffffffu, local, o);
        cnt   += __shfl_down_sync(0xffffffffu, cnt, o);
    }
    if (lane == 0) { red[wid] = local; redc[wid] = cnt; }
    __syncthreads();
    if (wid == 0) {
        float vv = (lane < WARPS) ? red[lane] : 0.0f;
        int   cc = (lane < WARPS) ? redc[lane] : 0;
        #pragma unroll
        for (int o = 8; o > 0; o >>= 1) {
            vv += __shfl_down_sync(0xffffffffu, vv, o);
            cc += __shfl_down_sync(0xffffffffu, cc, o);
        }
        if (lane == 0) {
            g_partial[cid] = vv;
            g_pcount[cid]  = cc;
            __threadfence();
            unsigned t = atomicAdd(&g_ticket, 1u);
            is_last = (t == NCHT - 1) ? 1 : 0;
        }
    }
    __syncthreads();

    // ---- 8. last block: stitch chunk boundaries + start/final, finalize ----
    if (is_last) {
        __threadfence();
        if (tid < B) {
            double s = 0.0; int c = 0, prv = -1, f0 = -1;
            #pragma unroll
            for (int k = 0; k < NCH; k++) {
                int idx = tid * NCH + k;
                s += (double)g_partial[idx];
                c += g_pcount[idx];
                int f = g_first[idx];
                if (f >= 0) {
                    if (prv >= 0)
                        s += (double)(A_sh[L + (prv - 1) * LP1 + (f - 1)] - lse_sh[prv - 1]);
                    else f0 = f;
                    prv = g_last[idx];
                }
            }
            if (f0 >= 0) {
                s += (double)(A_sh[f0 - 1] - lse_sh[L]);                        // start
                s += (double)(A_sh[L + (prv - 1) * LP1 + L] - lse_sh[prv - 1]); // final
            }
            row_sum[tid] = s;
            row_cnt[tid] = c;
        }
        __syncthreads();
        if (wid == 0) {
            double s = row_sum[lane] + row_sum[lane + 32];
            int    c = row_cnt[lane] + row_cnt[lane + 32];
            #pragma unroll
            for (int o = 16; o > 0; o >>= 1) {
                s += __shfl_down_sync(0xffffffffu, s, o);
                c += __shfl_down_sync(0xffffffffu, c, o);
            }
            if (lane == 0) {
                out[0] = (float)(s / (double)c);
                g_ticket = 0;    // reset for graph replay
            }
        }
    }
}

// ---------------------------------------------------------------------------
// Launch
// ---------------------------------------------------------------------------
extern "C" void kernel_launch(void* const* d_in, const int* in_sizes, int n_in,
                              void* d_out, int out_size) {
    const float* log_probs = (const float*)d_in[0];   // (B, S, C) f32
    const float* A_scores  = (const float*)d_in[1];   // (N_ARCS,) f32
    const int*   labels    = (const int*)d_in[2];     // (B, S) i32
    float* out = (float*)d_out;

    crf_fused_kernel<<<NCHT, THREADS>>>(log_probs, A_scores, labels, out);
}